// round 14
// baseline (speedup 1.0000x reference)
#include <cuda_runtime.h>
#include <cuda_fp16.h>
#include <cstdint>

#define Bb 32
#define Dd 20
#define Ll 4096
#define Kk 1000
#define Nn (Bb*Ll)
#define NDLs (Bb*Dd*Ll)
#define NUNITS (Nn/16)          // 8192 m16 tiles
#define NBLK 148
#define WPB 32
#define NTHR (WPB*32)           // 1024
#define NWARPS (NBLK*WPB)       // 4736
#define ROWW 20                 // words per code row (40 halves)
#define RWORDS (1024*ROWW)
#define SMEM_BYTES (2*RWORDS*4) // 163840 B

__device__ int   g_work;
__device__ float g_kl;
__device__ int   g_hist[Kk];
__device__ int   g_done;

// in-place accumulate: D and C share registers ("+f") -> no MOV shuffling
__device__ __forceinline__ void mma16(float* d, uint32_t a0, uint32_t a1, uint32_t a2, uint32_t a3,
                                      uint32_t b0, uint32_t b1){
  asm volatile("mma.sync.aligned.m16n8k16.row.col.f32.f16.f16.f32 "
    "{%0,%1,%2,%3},{%4,%5,%6,%7},{%8,%9},{%0,%1,%2,%3};"
    : "+f"(d[0]),"+f"(d[1]),"+f"(d[2]),"+f"(d[3])
    : "r"(a0),"r"(a1),"r"(a2),"r"(a3), "r"(b0),"r"(b1));
}
__device__ __forceinline__ void mma8(float* d, uint32_t a0, uint32_t a1, uint32_t b0){
  asm volatile("mma.sync.aligned.m16n8k8.row.col.f32.f16.f16.f32 "
    "{%0,%1,%2,%3},{%4,%5},{%6},{%0,%1,%2,%3};"
    : "+f"(d[0]),"+f"(d[1]),"+f"(d[2]),"+f"(d[3])
    : "r"(a0),"r"(a1), "r"(b0));
}
__device__ __forceinline__ void lds32(uint32_t& v, uint32_t a){
  asm volatile("ld.shared.b32 %0,[%1];" : "=r"(v) : "r"(a));
}
__device__ __forceinline__ uint32_t smem_u32(const void* p){
  uint32_t a; asm("{ .reg .u64 t; cvta.to.shared.u64 t, %1; cvt.u32.u64 %0, t; }" : "=r"(a) : "l"(p));
  return a;
}
__device__ __forceinline__ uint32_t packh(__half a, __half b){
  __half2 t = __halves2half2(a, b); return *(uint32_t*)&t;
}

__global__ void __launch_bounds__(NTHR,1) vq_main(const float* __restrict__ x,
                                                  const float* __restrict__ emb,
                                                  float* __restrict__ out, int out_size){
  extern __shared__ __half smh[];
  __half* Hh = smh;               // [1024*40] high parts, k-natural order, row stride 40 halves
  __half* Hm = smh + 2*RWORDS;    // [1024*40] mid (residual) parts
  __shared__ float swr[WPB];
  __shared__ int slast;
  const uint32_t sbase = smem_u32(smh);
  const uint32_t HB = sbase, MB = sbase + RWORDS*4;
  const int tid = threadIdx.x, lane = tid & 31, wid = tid >> 5;
  const int tg = lane & 3, g = lane >> 2;
  const uint32_t lanoff = (g*ROWW + tg)*4;

  // codebook fp16 h/m splits (aug k=20 -> -0.5||e||^2; pads zero; pad-codes bias -60000)
  for (int k = tid; k < 1024; k += NTHR){
    float e[Dd]; float nh;
    if (k < Kk){
      float s = 0.f;
      #pragma unroll
      for (int d = 0; d < Dd; d++){ e[d] = __ldg(emb + k*Dd + d); s = fmaf(e[d], e[d], s); }
      nh = -0.5f*s;
    } else {
      #pragma unroll
      for (int d = 0; d < Dd; d++) e[d] = 0.f;
      nh = -60000.f;
    }
    #pragma unroll
    for (int kk = 0; kk < 24; kk++){
      float v = (kk < Dd) ? e[kk] : ((kk == Dd) ? nh : 0.f);
      __half h = __float2half_rn(v);
      Hh[k*40 + kk] = h;
      Hm[k*40 + kk] = __float2half_rn(v - __half2float(h));
    }
  }
  __syncthreads();

  float klacc = 0.f;
  int u = blockIdx.x*WPB + wid;
  while (u < NUNITS){
    // A fragments (fp16 h/m): rows g, g+8; k = 2tg+{0,1,8,9,16,17}
    uint32_t AH[6], AM[6];
    {
      const int n0 = u*16 + g, n1 = n0 + 8;
      const float* p0 = x + (size_t)(n0 >> 12)*(Dd*Ll) + (n0 & (Ll-1));
      const float* p1 = x + (size_t)(n1 >> 12)*(Dd*Ll) + (n1 & (Ll-1));
      #pragma unroll
      for (int j = 0; j < 3; j++){               // k-pair groups: base 2tg + {0,8,16}
        const int ka = 2*tg + j*8, kb = ka + 1;
        float va0 = (ka < Dd) ? __ldg(p0 + ka*Ll) : ((ka == Dd) ? 1.f : 0.f);
        float vb0 = (kb < Dd) ? __ldg(p0 + kb*Ll) : ((kb == Dd) ? 1.f : 0.f);
        float va1 = (ka < Dd) ? __ldg(p1 + ka*Ll) : ((ka == Dd) ? 1.f : 0.f);
        float vb1 = (kb < Dd) ? __ldg(p1 + kb*Ll) : ((kb == Dd) ? 1.f : 0.f);
        __half ha0 = __float2half_rn(va0), hb0 = __float2half_rn(vb0);
        __half ha1 = __float2half_rn(va1), hb1 = __float2half_rn(vb1);
        AH[2*j]   = packh(ha0, hb0);
        AH[2*j+1] = packh(ha1, hb1);
        AM[2*j]   = packh(__float2half_rn(va0 - __half2float(ha0)), __float2half_rn(vb0 - __half2float(hb0)));
        AM[2*j+1] = packh(__float2half_rn(va1 - __half2float(ha1)), __float2half_rn(vb1 - __half2float(hb1)));
      }
    }

    float best0 = -3.4e38f, best1 = -3.4e38f;
    int   idx0 = 0, idx1 = 0;

    #pragma unroll 2
    for (int nb = 0; nb < 128; nb++){
      const uint32_t rb = (uint32_t)nb*(8u*ROWW*4u) + lanoff;
      uint32_t bh0, bh1, bh2, bm0, bm1, bm2;
      lds32(bh0, HB + rb); lds32(bh1, HB + rb + 16); lds32(bh2, HB + rb + 32);
      lds32(bm0, MB + rb); lds32(bm1, MB + rb + 16); lds32(bm2, MB + rb + 32);

      float d4[4] = {0.f, 0.f, 0.f, 0.f};
      mma16(d4, AH[0], AH[1], AH[2], AH[3], bh0, bh1);   // hh c1
      mma8 (d4, AH[4], AH[5], bh2);                      // hh c2 (k8)
      mma16(d4, AH[0], AH[1], AH[2], AH[3], bm0, bm1);   // hm c1
      mma8 (d4, AH[4], AH[5], bm2);                      // hm c2 (k8, incl bias_m)
      mma16(d4, AM[0], AM[1], AM[2], AM[3], bh0, bh1);   // mh c1
      mma8 (d4, AM[4], AM[5], bh2);                      // mh c2 (k8)

      const int c0 = nb*8 + 2*tg;
      float m0 = fmaxf(d4[0], d4[1]);
      if (m0 > best0){ best0 = m0; idx0 = c0 + ((d4[1] > d4[0]) ? 1 : 0); }
      float m1 = fmaxf(d4[2], d4[3]);
      if (m1 > best1){ best1 = m1; idx1 = c0 + ((d4[3] > d4[2]) ? 1 : 0); }
    }

    // reduce across the 4 lanes sharing each row
    #pragma unroll
    for (int off = 1; off <= 2; off <<= 1){
      float s0 = __shfl_xor_sync(0xFFFFFFFFu, best0, off);
      int   i0 = __shfl_xor_sync(0xFFFFFFFFu, idx0,  off);
      if (s0 > best0 || (s0 == best0 && i0 < idx0)){ best0 = s0; idx0 = i0; }
      float s1 = __shfl_xor_sync(0xFFFFFFFFu, best1, off);
      int   i1 = __shfl_xor_sync(0xFFFFFFFFu, idx1,  off);
      if (s1 > best1 || (s1 == best1 && i1 < idx1)){ best1 = s1; idx1 = i1; }
    }
    // distribute: lane j<16 gets code for point u*16+j
    const int src = (lane & 7)*4;
    const int c0s = __shfl_sync(0xFFFFFFFFu, idx0, src);
    const int c1s = __shfl_sync(0xFFFFFFFFu, idx1, src);

    if (lane < 16){
      const int code = (lane < 8) ? c0s : c1s;
      const int n = u*16 + lane;
      const int bb = n >> 12, l = n & (Ll-1);
      const float* xp = x + (size_t)bb*(Dd*Ll) + l;
      float* op = out + (size_t)bb*(Dd*Ll) + l;

      float mx = -3.4e38f, mq = -3.4e38f;
      #pragma unroll 4
      for (int d = 0; d < Dd; d++){
        float xv = __ldg(xp + d*Ll);
        float qv = __half2float(Hh[code*40 + d]) + __half2float(Hm[code*40 + d]);
        mx = fmaxf(mx, xv); mq = fmaxf(mq, qv);
      }
      float Sx = 0.f, Sq = 0.f, A = 0.f, Cr = 0.f;
      #pragma unroll 4
      for (int d = 0; d < Dd; d++){
        float xv = __ldg(xp + d*Ll);
        float qv = __half2float(Hh[code*40 + d]) + __half2float(Hm[code*40 + d]);
        op[d*Ll] = xv + (qv - xv);
        float xs = xv - mx;
        float ex = __expf(xs), eq = __expf(qv - mq);
        Sx += ex; Sq += eq;
        A  = fmaf(ex, xs, A);
        Cr = fmaf(ex, eq, Cr);
      }
      klacc += A/Sx - __logf(Sx) - Cr/(Sx*Sq);
      atomicAdd(&g_hist[code], 1);
    }

    if (lane == 0) u = NWARPS + atomicAdd(&g_work, 1);
    u = __shfl_sync(0xFFFFFFFFu, u, 0);
  }

  // block-level KL reduction, one atomic per block
  #pragma unroll
  for (int off = 16; off; off >>= 1) klacc += __shfl_xor_sync(0xFFFFFFFFu, klacc, off);
  if (lane == 0) swr[wid] = klacc;
  __syncthreads();
  if (tid == 0){
    float s = 0.f;
    #pragma unroll
    for (int w = 0; w < WPB; w++) s += swr[w];
    atomicAdd(&g_kl, s);
  }

  __threadfence();
  __syncthreads();
  if (tid == 0) slast = (atomicAdd(&g_done, 1) == NBLK - 1);
  __syncthreads();
  if (slast){
    float s = 0.f;
    for (int k = tid; k < Kk; k += NTHR){
      float a = (float)(*(volatile int*)&g_hist[k]) * (1.f/(float)Nn);
      s += a * logf(a + 1e-10f);
      g_hist[k] = 0;
    }
    #pragma unroll
    for (int off = 16; off; off >>= 1) s += __shfl_xor_sync(0xFFFFFFFFu, s, off);
    if (lane == 0) swr[wid] = s;
    __syncthreads();
    if (tid == 0){
      float t = 0.f;
      #pragma unroll
      for (int w = 0; w < WPB; w++) t += swr[w];
      if (out_size >= NDLs + 2){
        out[NDLs]     = 0.1f * ((*(volatile float*)&g_kl) / (float)Bb);
        out[NDLs + 1] = expf(-t);
      }
      g_kl = 0.f; g_done = 0; g_work = 0;
    }
  }
}

extern "C" void kernel_launch(void* const* d_in, const int* in_sizes, int n_in,
                              void* d_out, int out_size){
  const float* x   = (const float*)d_in[0];
  const float* emb = (const float*)d_in[1];
  float* out = (float*)d_out;
  cudaFuncSetAttribute(vq_main, cudaFuncAttributeMaxDynamicSharedMemorySize, SMEM_BYTES);
  vq_main<<<NBLK, NTHR, SMEM_BYTES>>>(x, emb, out, out_size);
}